// round 10
// baseline (speedup 1.0000x reference)
#include <cuda_runtime.h>

#define B_CHAIN 16384
#define S_SIDE 15
#define NATM (1 + B_CHAIN + B_CHAIN * S_SIDE)
#define GEN1_BASE (1 + B_CHAIN)

#define NBLK 256
#define TPB 256
#define NCHUNK 512                        // 32-atom warp chunks over the backbone
#define CHAINS_PER_BLK (B_CHAIN / NBLK)   // 64

// Scratch (static __device__ arrays — no allocation).
__device__ __align__(16) float g_scan[(B_CHAIN + 1) * 12];  // within-chunk inclusive
__device__ __align__(16) float g_blk[NCHUNK * 12];          // chunk totals
__device__ unsigned g_arrive;   // zero-init; self-resetting each launch
__device__ unsigned g_depart;

// Affine 3x4: m[0..8] row-major rotation, m[9..11] translation. c = a*b (a earlier).
__device__ __forceinline__ void aff_mul(const float a[12], const float b[12], float c[12]) {
#pragma unroll
    for (int i = 0; i < 3; i++) {
        float a0 = a[i * 3 + 0], a1 = a[i * 3 + 1], a2 = a[i * 3 + 2];
        float t  = a[9 + i];
        c[i * 3 + 0] = a0 * b[0] + a1 * b[3] + a2 * b[6];
        c[i * 3 + 1] = a0 * b[1] + a1 * b[4] + a2 * b[7];
        c[i * 3 + 2] = a0 * b[2] + a1 * b[5] + a2 * b[8];
        c[9 + i]     = a0 * b[9] + a1 * b[10] + a2 * b[11] + t;
    }
}

__device__ __forceinline__ void aff_identity(float m[12]) {
#pragma unroll
    for (int k = 0; k < 12; k++) m[k] = 0.0f;
    m[0] = m[4] = m[8] = 1.0f;
}

// ht_bond = Rx(p)*Rz(t)*T(d,0,0)*Rx(c), collapsed. Precise trig (backbone).
__device__ __forceinline__ void make_bond(float p, float t, float d, float c, float m[12]) {
    float sp, cp, st, ct, sc, cc;
    sincosf(p, &sp, &cp);
    sincosf(t, &st, &ct);
    sincosf(c, &sc, &cc);
    m[0] = ct;        m[1] = -st * cc;               m[2] = st * sc;
    m[3] = cp * st;   m[4] = cp * ct * cc - sp * sc; m[5] = -cp * ct * sc - sp * cc;
    m[6] = sp * st;   m[7] = sp * ct * cc + cp * sc; m[8] = -sp * ct * sc + cp * cc;
    m[9] = ct * d;    m[10] = cp * st * d;           m[11] = sp * st * d;
}

// Fast-trig variant (side chains: 15-product chains, no accumulation).
__device__ __forceinline__ void make_bond_fast(float p, float t, float d, float c, float m[12]) {
    float sp, cp, st, ct, sc, cc;
    __sincosf(p, &sp, &cp);
    __sincosf(t, &st, &ct);
    __sincosf(c, &sc, &cc);
    m[0] = ct;        m[1] = -st * cc;               m[2] = st * sc;
    m[3] = cp * st;   m[4] = cp * ct * cc - sp * sc; m[5] = -cp * ct * sc - sp * cc;
    m[6] = sp * st;   m[7] = sp * ct * cc + cp * sc; m[8] = -sp * ct * sc + cp * cc;
    m[9] = ct * d;    m[10] = cp * st * d;           m[11] = sp * st * d;
}

__device__ __forceinline__ void make_ht(int atom, float4 dv, float m[12]) {
    if (atom == 1) {   // jump node: T(d0,d1,d2)*Rx(d3)
        float sc, cc;
        sincosf(dv.w, &sc, &cc);
        m[0] = 1.f; m[1] = 0.f; m[2] = 0.f;
        m[3] = 0.f; m[4] = cc;  m[5] = -sc;
        m[6] = 0.f; m[7] = sc;  m[8] = cc;
        m[9] = dv.x; m[10] = dv.y; m[11] = dv.z;
    } else {
        make_bond(dv.x, dv.y, dv.z, dv.w, m);
    }
}

__device__ __forceinline__ void store12(float* dst, const float m[12]) {
    float4* d4 = (float4*)dst;
    d4[0] = make_float4(m[0], m[1], m[2], m[3]);
    d4[1] = make_float4(m[4], m[5], m[6], m[7]);
    d4[2] = make_float4(m[8], m[9], m[10], m[11]);
}

__device__ __forceinline__ void load12(const float* src, float m[12]) {
    const float4* s4 = (const float4*)src;
    float4 a = s4[0], b = s4[1], c = s4[2];
    m[0] = a.x; m[1] = a.y; m[2] = a.z; m[3] = a.w;
    m[4] = b.x; m[5] = b.y; m[6] = b.z; m[7] = b.w;
    m[8] = c.x; m[9] = c.y; m[10] = c.z; m[11] = c.w;
}

// Scalar 3-store coordinate write (no alignment assumption on `out`).
__device__ __forceinline__ void store_coord(float* __restrict__ out, int kid,
                                            float x, float y, float z) {
    float* p = out + kid * 3;
    p[0] = x;
    p[1] = y;
    p[2] = z;
}

// Warp-level inclusive Kogge-Stone (32 lanes), no barriers.
__device__ __forceinline__ void warp_scan32(float P[12], int lane) {
#pragma unroll
    for (int d = 1; d < 32; d <<= 1) {
        float L[12];
#pragma unroll
        for (int k = 0; k < 12; k++)
            L[k] = __shfl_up_sync(0xffffffffu, P[k], d, 32);
        if (lane >= d) {
            float T[12];
            aff_mul(L, P, T);
#pragma unroll
            for (int k = 0; k < 12; k++) P[k] = T[k];
        }
    }
}

// Self-resetting grid barrier with nanosleep backoff.
__device__ __forceinline__ void grid_barrier() {
    __syncthreads();
    if (threadIdx.x == 0) {
        __threadfence();
        atomicAdd(&g_arrive, 1u);
        volatile unsigned* va = &g_arrive;
        while (*va < (unsigned)NBLK) { __nanosleep(64); }
        __threadfence();
        unsigned d = atomicAdd(&g_depart, 1u);
        if (d == (unsigned)NBLK - 1u) {
            g_arrive = 0u;
            g_depart = 0u;
            __threadfence();
        }
    }
    __syncthreads();
}

// ---------------------------------------------------------------------------
// Single fused persistent kernel. 256 blocks x 256 threads, all co-resident.
// ---------------------------------------------------------------------------
__global__ void __launch_bounds__(TPB, 2) k_fused(const float* __restrict__ dofs,
                                                  const int* __restrict__ kin_id,
                                                  float* __restrict__ out) {
    __shared__ float wt[8 * 12];     // per-warp totals for phase-2 combine
    __shared__ float sPreA[12];      // exclusive prefix for chunk 2b
    __shared__ float sPreB[12];      // exclusive prefix for chunk 2b+1
    int t = threadIdx.x;
    int b = blockIdx.x;
    int w = t >> 5, l = t & 31;

    // Phase-3 identity of this thread (computed up front for prefetch)
    int c = b * CHAINS_PER_BLK + (t >> 2);   // chain id
    int r = t & 3;                            // rake lane

    // ===== Prefetch the dof vectors this thread needs in phase 3 =====
    const float4* dof4 = (const float4*)dofs;
    float4 dv0, dv1, dv2, dv3;
    {
        int nb = GEN1_BASE + c * S_SIDE + 4 * r - 1;   // node of element 4r (r>0)
        if (r > 0) dv0 = dof4[nb - 1];
        dv1 = dof4[nb + 0];
        dv2 = dof4[nb + 1];
        dv3 = dof4[nb + 2];
    }

    // ===== Phase 1: backbone chunk scans, spread across ALL blocks =====
    // chunk = 2*b + w for w<2 -> every block has 2 active warps.
    if (w < 2) {
        int chunk = 2 * b + w;
        int atom = chunk * 32 + l + 1;
        float4 dv = dof4[atom - 1];
        float P[12];
        make_ht(atom, dv, P);
        warp_scan32(P, l);
        store12(g_scan + atom * 12, P);
        if (l == 31) store12(g_blk + chunk * 12, P);
    }

    // ===== grid barrier =====
    grid_barrier();

    // ===== Prefetch lane-0's g_scan row (consumed in phase 3) =====
    float Sv[12];
    if (r == 0) load12(g_scan + (c + 1) * 12, Sv);

    // ===== Phase 2: redundant prefix of the 512 chunk totals =====
    {
        float A[12], Bm[12], Q[12];
        load12(g_blk + (2 * t) * 12, A);
        load12(g_blk + (2 * t + 1) * 12, Bm);
        aff_mul(A, Bm, Q);
        warp_scan32(Q, l);
        if (l == 31) {
#pragma unroll
            for (int k = 0; k < 12; k++) wt[w * 12 + k] = Q[k];
        }
        __syncthreads();
        if (w == 0 && l < 8) {          // scan 8 warp totals
            float W[12];
#pragma unroll
            for (int k = 0; k < 12; k++) W[k] = wt[l * 12 + k];
#pragma unroll
            for (int d = 1; d < 8; d <<= 1) {
                float L[12];
#pragma unroll
                for (int k = 0; k < 12; k++)
                    L[k] = __shfl_up_sync(0x000000ffu, W[k], d, 32);
                if (l >= d) {
                    float T[12];
                    aff_mul(L, W, T);
#pragma unroll
                    for (int k = 0; k < 12; k++) W[k] = T[k];
                }
            }
#pragma unroll
            for (int k = 0; k < 12; k++) wt[l * 12 + k] = W[k];
        }
        __syncthreads();
        if (w > 0) {
            float E[12], T[12];
#pragma unroll
            for (int k = 0; k < 12; k++) E[k] = wt[(w - 1) * 12 + k];
            aff_mul(E, Q, T);
#pragma unroll
            for (int k = 0; k < 12; k++) Q[k] = T[k];
        }
        // Q is now Inc[t] (product of chunks 0..2t+1). Block needs Inc[b-1].
        if (b == 0) {
            if (t == 0) {
                float I[12];
                aff_identity(I);
#pragma unroll
                for (int k = 0; k < 12; k++) sPreA[k] = I[k];
            }
        } else if (t == b - 1) {
#pragma unroll
            for (int k = 0; k < 12; k++) sPreA[k] = Q[k];
        }
        __syncthreads();
        if (t == 0) {   // prefix for chunk 2b+1 = preA * blk[2b]
            float C0[12], T[12];
            load12(g_blk + (2 * b) * 12, C0);
            float preA[12];
#pragma unroll
            for (int k = 0; k < 12; k++) preA[k] = sPreA[k];
            aff_mul(preA, C0, T);
#pragma unroll
            for (int k = 0; k < 12; k++) sPreB[k] = T[k];
        }
        __syncthreads();
    }

    // ===== Phase 3: rake side chains (64 chains/block, 4 lanes each) =====
    float E0[12];
    if (r == 0) {
        float pre[12];
        const float* ps = (t < 128) ? sPreA : sPreB;
#pragma unroll
        for (int k = 0; k < 12; k++) pre[k] = ps[k];
        aff_mul(pre, Sv, E0);                 // parent global transform
    } else {
        make_bond_fast(dv0.x, dv0.y, dv0.z, dv0.w, E0);
    }

    // phase 3a: build + CACHE the 3 bond matrices, dense serial product
    float M1[12], M2[12], M3[12];
    make_bond_fast(dv1.x, dv1.y, dv1.z, dv1.w, M1);
    make_bond_fast(dv2.x, dv2.y, dv2.z, dv2.w, M2);
    make_bond_fast(dv3.x, dv3.y, dv3.z, dv3.w, M3);

    float P[12];
    {
        float T[12];
        aff_mul(E0, M1, T);
        aff_mul(T, M2, P);
        aff_mul(P, M3, T);
#pragma unroll
        for (int k = 0; k < 12; k++) P[k] = T[k];
    }

    // phase 3b: width-4 inclusive scan (2 steps)
#pragma unroll
    for (int d = 1; d < 4; d <<= 1) {
        float L[12];
#pragma unroll
        for (int k = 0; k < 12; k++)
            L[k] = __shfl_up_sync(0xffffffffu, P[k], d, 4);
        if (r >= d) {
            float T[12];
            aff_mul(L, P, T);
#pragma unroll
            for (int k = 0; k < 12; k++) P[k] = T[k];
        }
    }

    // exclusive prefix for this lane
    float X[12];
#pragma unroll
    for (int k = 0; k < 12; k++) X[k] = __shfl_up_sync(0xffffffffu, P[k], 1, 4);
    if (r == 0) aff_identity(X);

    // phase 3c: apply cached bonds + emit 4 prefix translations
    int node0 = (r == 0) ? (c + 1) : (GEN1_BASE + c * S_SIDE + (4 * r - 1));
    int nodeS = GEN1_BASE + c * S_SIDE + 4 * r;   // nodes for j=1..3 are nodeS, +1, +2

    float G[12];
    {
        float T[12];
        aff_mul(X, E0, T);
#pragma unroll
        for (int k = 0; k < 12; k++) G[k] = T[k];
    }
    store_coord(out, kin_id[node0], G[9], G[10], G[11]);
    {
        float T[12];
        aff_mul(G, M1, T);
#pragma unroll
        for (int k = 0; k < 12; k++) G[k] = T[k];
        store_coord(out, kin_id[nodeS + 0], G[9], G[10], G[11]);
        aff_mul(G, M2, T);
#pragma unroll
        for (int k = 0; k < 12; k++) G[k] = T[k];
        store_coord(out, kin_id[nodeS + 1], G[9], G[10], G[11]);
        aff_mul(G, M3, T);
#pragma unroll
        for (int k = 0; k < 12; k++) G[k] = T[k];
        store_coord(out, kin_id[nodeS + 2], G[9], G[10], G[11]);
    }
}

extern "C" void kernel_launch(void* const* d_in, const int* in_sizes, int n_in,
                              void* d_out, int out_size) {
    const float* dofs   = (const float*)d_in[0];
    const int*   kin_id = (const int*)d_in[8];
    float*       out    = (float*)d_out;

    k_fused<<<NBLK, TPB>>>(dofs, kin_id, out);
}

// round 11
// speedup vs baseline: 1.0323x; 1.0323x over previous
#include <cuda_runtime.h>

#define B_CHAIN 16384
#define S_SIDE 15
#define NATM (1 + B_CHAIN + B_CHAIN * S_SIDE)
#define GEN1_BASE (1 + B_CHAIN)

#define NBLK 296                 // 148 SMs x 2 blocks, all co-resident
#define TPB 256
#define NCHUNK 512               // 32-atom warp chunks over the backbone
#define CHAINS_PER_BLK 56        // ceil(16384/296); tail guarded

// Scratch (static __device__ arrays — no allocation).
__device__ __align__(16) float g_scan[(B_CHAIN + 1) * 12];  // within-chunk inclusive
__device__ __align__(16) float g_blk[NCHUNK * 12];          // chunk totals
__device__ unsigned g_arrive;   // zero-init; self-resetting each launch
__device__ unsigned g_depart;

// Affine 3x4: m[0..8] row-major rotation, m[9..11] translation. c = a*b (a earlier).
__device__ __forceinline__ void aff_mul(const float a[12], const float b[12], float c[12]) {
#pragma unroll
    for (int i = 0; i < 3; i++) {
        float a0 = a[i * 3 + 0], a1 = a[i * 3 + 1], a2 = a[i * 3 + 2];
        float t  = a[9 + i];
        c[i * 3 + 0] = a0 * b[0] + a1 * b[3] + a2 * b[6];
        c[i * 3 + 1] = a0 * b[1] + a1 * b[4] + a2 * b[7];
        c[i * 3 + 2] = a0 * b[2] + a1 * b[5] + a2 * b[8];
        c[9 + i]     = a0 * b[9] + a1 * b[10] + a2 * b[11] + t;
    }
}

__device__ __forceinline__ void aff_identity(float m[12]) {
#pragma unroll
    for (int k = 0; k < 12; k++) m[k] = 0.0f;
    m[0] = m[4] = m[8] = 1.0f;
}

// ht_bond = Rx(p)*Rz(t)*T(d,0,0)*Rx(c), collapsed. Precise trig (backbone).
__device__ __forceinline__ void make_bond(float p, float t, float d, float c, float m[12]) {
    float sp, cp, st, ct, sc, cc;
    sincosf(p, &sp, &cp);
    sincosf(t, &st, &ct);
    sincosf(c, &sc, &cc);
    m[0] = ct;        m[1] = -st * cc;               m[2] = st * sc;
    m[3] = cp * st;   m[4] = cp * ct * cc - sp * sc; m[5] = -cp * ct * sc - sp * cc;
    m[6] = sp * st;   m[7] = sp * ct * cc + cp * sc; m[8] = -sp * ct * sc + cp * cc;
    m[9] = ct * d;    m[10] = cp * st * d;           m[11] = sp * st * d;
}

// Fast-trig variant (side chains: 15-product chains, no accumulation).
__device__ __forceinline__ void make_bond_fast(float p, float t, float d, float c, float m[12]) {
    float sp, cp, st, ct, sc, cc;
    __sincosf(p, &sp, &cp);
    __sincosf(t, &st, &ct);
    __sincosf(c, &sc, &cc);
    m[0] = ct;        m[1] = -st * cc;               m[2] = st * sc;
    m[3] = cp * st;   m[4] = cp * ct * cc - sp * sc; m[5] = -cp * ct * sc - sp * cc;
    m[6] = sp * st;   m[7] = sp * ct * cc + cp * sc; m[8] = -sp * ct * sc + cp * cc;
    m[9] = ct * d;    m[10] = cp * st * d;           m[11] = sp * st * d;
}

__device__ __forceinline__ void make_ht(int atom, float4 dv, float m[12]) {
    if (atom == 1) {   // jump node: T(d0,d1,d2)*Rx(d3)
        float sc, cc;
        sincosf(dv.w, &sc, &cc);
        m[0] = 1.f; m[1] = 0.f; m[2] = 0.f;
        m[3] = 0.f; m[4] = cc;  m[5] = -sc;
        m[6] = 0.f; m[7] = sc;  m[8] = cc;
        m[9] = dv.x; m[10] = dv.y; m[11] = dv.z;
    } else {
        make_bond(dv.x, dv.y, dv.z, dv.w, m);
    }
}

__device__ __forceinline__ void store12(float* dst, const float m[12]) {
    float4* d4 = (float4*)dst;
    d4[0] = make_float4(m[0], m[1], m[2], m[3]);
    d4[1] = make_float4(m[4], m[5], m[6], m[7]);
    d4[2] = make_float4(m[8], m[9], m[10], m[11]);
}

__device__ __forceinline__ void load12(const float* src, float m[12]) {
    const float4* s4 = (const float4*)src;
    float4 a = s4[0], b = s4[1], c = s4[2];
    m[0] = a.x; m[1] = a.y; m[2] = a.z; m[3] = a.w;
    m[4] = b.x; m[5] = b.y; m[6] = b.z; m[7] = b.w;
    m[8] = c.x; m[9] = c.y; m[10] = c.z; m[11] = c.w;
}

// Scalar 3-store coordinate write (no alignment assumption on `out`).
__device__ __forceinline__ void store_coord(float* __restrict__ out, int kid,
                                            float x, float y, float z) {
    float* p = out + kid * 3;
    p[0] = x;
    p[1] = y;
    p[2] = z;
}

// Warp-level inclusive Kogge-Stone (32 lanes), no barriers.
__device__ __forceinline__ void warp_scan32(float P[12], int lane) {
#pragma unroll
    for (int d = 1; d < 32; d <<= 1) {
        float L[12];
#pragma unroll
        for (int k = 0; k < 12; k++)
            L[k] = __shfl_up_sync(0xffffffffu, P[k], d, 32);
        if (lane >= d) {
            float T[12];
            aff_mul(L, P, T);
#pragma unroll
            for (int k = 0; k < 12; k++) P[k] = T[k];
        }
    }
}

// Self-resetting grid barrier with nanosleep backoff.
__device__ __forceinline__ void grid_barrier() {
    __syncthreads();
    if (threadIdx.x == 0) {
        __threadfence();
        atomicAdd(&g_arrive, 1u);
        volatile unsigned* va = &g_arrive;
        while (*va < (unsigned)NBLK) { __nanosleep(64); }
        __threadfence();
        unsigned d = atomicAdd(&g_depart, 1u);
        if (d == (unsigned)NBLK - 1u) {
            g_arrive = 0u;
            g_depart = 0u;
            __threadfence();
        }
    }
    __syncthreads();
}

// ---------------------------------------------------------------------------
// Single fused persistent kernel. 296 blocks x 256 threads, 2 blocks/SM.
// ---------------------------------------------------------------------------
__global__ void __launch_bounds__(TPB, 2) k_fused(const float* __restrict__ dofs,
                                                  const int* __restrict__ kin_id,
                                                  float* __restrict__ out) {
    __shared__ float wt[8 * 12];            // per-warp totals for phase-2 combine
    __shared__ float sInc[(TPB) * 12];      // IncPair[t] staging (12KB)
    __shared__ float sPre[NCHUNK * 12];     // exclusive prefix per chunk (24KB)
    int t = threadIdx.x;
    int b = blockIdx.x;
    int w = t >> 5, l = t & 31;

    // Phase-3 identity (computed up front for prefetch)
    int c = b * CHAINS_PER_BLK + (t >> 2);   // chain id
    int r = t & 3;                            // rake lane
    bool active = (t < CHAINS_PER_BLK * 4) && (c < B_CHAIN);

    // ===== Prefetch dof vectors + kin_id this thread needs in phase 3 =====
    const float4* dof4 = (const float4*)dofs;
    float4 dv0, dv1, dv2, dv3;
    int kid0 = 0, kid1 = 0, kid2 = 0, kid3 = 0;
    if (active) {
        int nb = GEN1_BASE + c * S_SIDE + 4 * r - 1;   // node of element 4r (r>0)
        if (r > 0) dv0 = dof4[nb - 1];
        dv1 = dof4[nb + 0];
        dv2 = dof4[nb + 1];
        dv3 = dof4[nb + 2];
        int node0 = (r == 0) ? (c + 1) : nb;
        kid0 = kin_id[node0];
        kid1 = kin_id[nb + 1];
        kid2 = kin_id[nb + 2];
        kid3 = kin_id[nb + 3];
    }

    // ===== Phase 1: backbone chunk scans (blocks 0..255, 2 warps each) =====
    if (b < 256 && w < 2) {
        int chunk = 2 * b + w;
        int atom = chunk * 32 + l + 1;
        float4 dv = dof4[atom - 1];
        float P[12];
        make_ht(atom, dv, P);
        warp_scan32(P, l);
        store12(g_scan + atom * 12, P);
        if (l == 31) store12(g_blk + chunk * 12, P);
    }

    // ===== grid barrier =====
    grid_barrier();

    // ===== Prefetch lane-0's g_scan row (consumed in phase 3) =====
    float Sv[12];
    if (active && r == 0) load12(g_scan + (c + 1) * 12, Sv);

    // ===== Phase 2: redundant prefix of the 512 chunk totals =====
    // Thread t owns chunk pair (2t, 2t+1). Produces sPre[chunk] for all 512.
    {
        float A[12], Bm[12], Q[12];
        load12(g_blk + (2 * t) * 12, A);
        load12(g_blk + (2 * t + 1) * 12, Bm);
        aff_mul(A, Bm, Q);
        warp_scan32(Q, l);
        if (l == 31) {
#pragma unroll
            for (int k = 0; k < 12; k++) wt[w * 12 + k] = Q[k];
        }
        __syncthreads();
        if (w == 0 && l < 8) {          // scan 8 warp totals
            float W[12];
#pragma unroll
            for (int k = 0; k < 12; k++) W[k] = wt[l * 12 + k];
#pragma unroll
            for (int d = 1; d < 8; d <<= 1) {
                float L[12];
#pragma unroll
                for (int k = 0; k < 12; k++)
                    L[k] = __shfl_up_sync(0x000000ffu, W[k], d, 32);
                if (l >= d) {
                    float T[12];
                    aff_mul(L, W, T);
#pragma unroll
                    for (int k = 0; k < 12; k++) W[k] = T[k];
                }
            }
#pragma unroll
            for (int k = 0; k < 12; k++) wt[l * 12 + k] = W[k];
        }
        __syncthreads();
        if (w > 0) {
            float E[12], T[12];
#pragma unroll
            for (int k = 0; k < 12; k++) E[k] = wt[(w - 1) * 12 + k];
            aff_mul(E, Q, T);
#pragma unroll
            for (int k = 0; k < 12; k++) Q[k] = T[k];
        }
        // Q = IncPair[t] = product of chunks 0..2t+1.
#pragma unroll
        for (int k = 0; k < 12; k++) sInc[t * 12 + k] = Q[k];
        __syncthreads();

        // pre[2t] = IncPair[t-1] (identity for t=0); pre[2t+1] = pre[2t]*blk[2t]
        float pe[12], po[12];
        if (t == 0) {
            aff_identity(pe);
        } else {
#pragma unroll
            for (int k = 0; k < 12; k++) pe[k] = sInc[(t - 1) * 12 + k];
        }
        aff_mul(pe, A, po);
#pragma unroll
        for (int k = 0; k < 12; k++) {
            sPre[(2 * t) * 12 + k]     = pe[k];
            sPre[(2 * t + 1) * 12 + k] = po[k];
        }
        __syncthreads();
    }

    if (!active) return;

    // ===== Phase 3: rake side chains (<=56 chains/block, 4 lanes each) =====
    float E0[12];
    if (r == 0) {
        // parent global = sPre[chunk of atom c+1] * g_scan[c+1]; chunk = c>>5
        float pre[12];
#pragma unroll
        for (int k = 0; k < 12; k++) pre[k] = sPre[(c >> 5) * 12 + k];
        aff_mul(pre, Sv, E0);
    } else {
        make_bond_fast(dv0.x, dv0.y, dv0.z, dv0.w, E0);
    }

    // phase 3a: build + cache the 3 bond matrices, dense serial product
    float M1[12], M2[12], M3[12];
    make_bond_fast(dv1.x, dv1.y, dv1.z, dv1.w, M1);
    make_bond_fast(dv2.x, dv2.y, dv2.z, dv2.w, M2);
    make_bond_fast(dv3.x, dv3.y, dv3.z, dv3.w, M3);

    float P[12];
    {
        float T[12];
        aff_mul(E0, M1, T);
        aff_mul(T, M2, P);
        aff_mul(P, M3, T);
#pragma unroll
        for (int k = 0; k < 12; k++) P[k] = T[k];
    }

    // phase 3b: width-4 inclusive scan (2 steps)
#pragma unroll
    for (int d = 1; d < 4; d <<= 1) {
        float L[12];
#pragma unroll
        for (int k = 0; k < 12; k++)
            L[k] = __shfl_up_sync(0xffffffffu, P[k], d, 4);
        if (r >= d) {
            float T[12];
            aff_mul(L, P, T);
#pragma unroll
            for (int k = 0; k < 12; k++) P[k] = T[k];
        }
    }

    // exclusive prefix for this lane
    float X[12];
#pragma unroll
    for (int k = 0; k < 12; k++) X[k] = __shfl_up_sync(0xffffffffu, P[k], 1, 4);
    if (r == 0) aff_identity(X);

    // phase 3c: apply cached bonds + emit 4 prefix translations
    float G[12];
    {
        float T[12];
        aff_mul(X, E0, T);
#pragma unroll
        for (int k = 0; k < 12; k++) G[k] = T[k];
    }
    store_coord(out, kid0, G[9], G[10], G[11]);
    {
        float T[12];
        aff_mul(G, M1, T);
#pragma unroll
        for (int k = 0; k < 12; k++) G[k] = T[k];
        store_coord(out, kid1, G[9], G[10], G[11]);
        aff_mul(G, M2, T);
#pragma unroll
        for (int k = 0; k < 12; k++) G[k] = T[k];
        store_coord(out, kid2, G[9], G[10], G[11]);
        aff_mul(G, M3, T);
#pragma unroll
        for (int k = 0; k < 12; k++) G[k] = T[k];
        store_coord(out, kid3, G[9], G[10], G[11]);
    }
}

extern "C" void kernel_launch(void* const* d_in, const int* in_sizes, int n_in,
                              void* d_out, int out_size) {
    const float* dofs   = (const float*)d_in[0];
    const int*   kin_id = (const int*)d_in[8];
    float*       out    = (float*)d_out;

    k_fused<<<NBLK, TPB>>>(dofs, kin_id, out);
}